// round 6
// baseline (speedup 1.0000x reference)
#include <cuda_runtime.h>

#define DIM    64
#define NTYPE  16
#define NMAX   100000
#define PAD    64          // max in-degree (Poisson(10): P(>=64) ~ 1e-30)
#define PAD_T  8192        // max nodes per type (Binomial(100k,1/16) max ~ 6.6k)
#define TILE_M 128
#define TILES_PER_TYPE (PAD_T / TILE_M)   // 64
#define AS_LD  140         // 140 mod 32 = 12 -> 4-way max STS conflict; 16B-aligned rows

// ---- scratch (device globals; allocation is forbidden) ----
__device__ int g_zero_region[NMAX + NTYPE];   // [0,NMAX)=deg cnt, [NMAX,..)=type cnt
#define G_CNT(i)  g_zero_region[i]
#define G_TCNT(t) g_zero_region[NMAX + (t)]

__device__ int g_bucket[(size_t)NMAX * PAD];  // 25.6 MB padded per-dst src lists
__device__ int g_tperm[NTYPE * PAD_T];        // type-sorted node ids

typedef unsigned long long u64;

__device__ __forceinline__ void fma_f32x2(u64& d, u64 a, u64 b, u64 c) {
    asm("fma.rn.f32x2 %0, %1, %2, %3;" : "=l"(d) : "l"(a), "l"(b), "l"(c));
}
__device__ __forceinline__ u64 dup_f32x2(float v) {
    u64 r; unsigned u = __float_as_uint(v);
    asm("mov.b64 %0, {%1, %1};" : "=l"(r) : "r"(u));
    return r;
}

// ---------------------------------------------------------------------------
// K1: single-pass bucketing. Edges -> padded per-dst buckets; nodes -> padded
//     per-type perm via block-aggregated smem atomics.
// ---------------------------------------------------------------------------
__global__ void bucket_all(const int* __restrict__ src,
                           const int* __restrict__ dst,
                           const int* __restrict__ ntype2, int e, int n) {
    __shared__ int h[NTYPE];
    __shared__ int hbase[NTYPE];

    int stride = gridDim.x * blockDim.x;
    int tid = blockIdx.x * blockDim.x + threadIdx.x;

    for (int i = tid; i < e; i += stride) {
        int d = dst[i];
        int s = src[i];
        int pos = atomicAdd(&G_CNT(d), 1);
        if (pos < PAD) g_bucket[(size_t)d * PAD + pos] = s;
    }

    if (threadIdx.x < NTYPE) h[threadIdx.x] = 0;
    __syncthreads();

    int per_block = (n + gridDim.x - 1) / gridDim.x;
    int nb = blockIdx.x * per_block;
    int ne = min(nb + per_block, n);

    for (int i = nb + threadIdx.x; i < ne; i += blockDim.x)
        atomicAdd(&h[ntype2[i]], 1);
    __syncthreads();
    if (threadIdx.x < NTYPE) {
        if (h[threadIdx.x] > 0)
            hbase[threadIdx.x] = atomicAdd(&G_TCNT(threadIdx.x), h[threadIdx.x]);
        h[threadIdx.x] = 0;
    }
    __syncthreads();
    for (int i = nb + threadIdx.x; i < ne; i += blockDim.x) {
        int t = ntype2[i];
        int lp = atomicAdd(&h[t], 1);
        int p = hbase[t] + lp;
        if (p < PAD_T) g_tperm[t * PAD_T + p] = i;
    }
}

// ---------------------------------------------------------------------------
// K2: FUSED gather-mean + per-type GEMM.
//   Block = one 128-node tile of one type.
//   Phase 1: 8 warps gather neighbor feat rows from padded buckets, mean,
//            write transposed into smem As[k][node] (lane owns k=lane,lane+32).
//   Phase 2: 128x64x64 GEMM with packed fma.rn.f32x2 (2x fp32 throughput).
// ---------------------------------------------------------------------------
__global__ void __launch_bounds__(256) fused_kernel(
        const float* __restrict__ feat,
        const float* __restrict__ gate_W,
        const float* __restrict__ gate_b,
        float* __restrict__ out) {
    int t    = blockIdx.x / TILES_PER_TYPE;
    int tile = blockIdx.x % TILES_PER_TYPE;

    int tcnt  = min(G_TCNT(t), PAD_T);
    int start = tile * TILE_M;
    if (start >= tcnt) return;
    int cnt = min(TILE_M, tcnt - start);

    extern __shared__ float sm[];
    float* Wsh = sm;                    // [64][64]  16 KB
    float* As  = sm + DIM * DIM;        // [64][AS_LD] 35.8 KB, transposed A
    __shared__ int   psh[TILE_M];
    __shared__ float bsh[DIM];

    if (threadIdx.x < TILE_M)
        psh[threadIdx.x] = (threadIdx.x < cnt)
            ? g_tperm[t * PAD_T + start + threadIdx.x] : -1;
    const float* Wt = gate_W + (size_t)t * DIM * DIM;
    for (int i = threadIdx.x; i < DIM * DIM; i += 256)
        Wsh[i] = Wt[i];
    if (threadIdx.x < DIM)
        bsh[threadIdx.x] = gate_b[t * DIM + threadIdx.x];
    __syncthreads();

    // ---- Phase 1: gather-mean into transposed As ----
    int w    = threadIdx.x >> 5;
    int lane = threadIdx.x & 31;

    for (int local = w; local < TILE_M; local += 8) {
        int node = psh[local];
        float alo0 = 0.f, ahi0 = 0.f, alo1 = 0.f, ahi1 = 0.f;
        int deg = 0;
        if (node >= 0) {
            deg = G_CNT(node);
            int c = min(deg, PAD);
            const int* row = g_bucket + (size_t)node * PAD;
            int j = 0;
            for (; j + 4 <= c; j += 4) {
                int s0 = __ldg(&row[j]);
                int s1 = __ldg(&row[j + 1]);
                int s2 = __ldg(&row[j + 2]);
                int s3 = __ldg(&row[j + 3]);
                const float* f0 = feat + s0 * DIM;
                const float* f1 = feat + s1 * DIM;
                const float* f2 = feat + s2 * DIM;
                const float* f3 = feat + s3 * DIM;
                float l0 = __ldg(f0 + lane), h0 = __ldg(f0 + 32 + lane);
                float l1 = __ldg(f1 + lane), h1 = __ldg(f1 + 32 + lane);
                float l2 = __ldg(f2 + lane), h2 = __ldg(f2 + 32 + lane);
                float l3 = __ldg(f3 + lane), h3 = __ldg(f3 + 32 + lane);
                alo0 += l0 + l1;  ahi0 += h0 + h1;
                alo1 += l2 + l3;  ahi1 += h2 + h3;
            }
            for (; j < c; j++) {
                int s0 = __ldg(&row[j]);
                alo0 += __ldg(feat + s0 * DIM + lane);
                ahi0 += __ldg(feat + s0 * DIM + 32 + lane);
            }
        }
        float invd = (deg > 0) ? (1.0f / (float)deg) : 0.0f;
        As[lane * AS_LD + local]        = (alo0 + alo1) * invd;
        As[(lane + 32) * AS_LD + local] = (ahi0 + ahi1) * invd;
    }
    __syncthreads();

    // ---- Phase 2: GEMM, thread = 4 nodes x 8 outs, packed f32x2 FMA ----
    int tx = threadIdx.x & 31;
    int ty = threadIdx.x >> 5;

    u64 acc[4][4];
    {
        ulonglong2 b01 = *reinterpret_cast<ulonglong2*>(&bsh[ty * 8]);
        ulonglong2 b23 = *reinterpret_cast<ulonglong2*>(&bsh[ty * 8 + 4]);
        #pragma unroll
        for (int i = 0; i < 4; i++) {
            acc[i][0] = b01.x; acc[i][1] = b01.y;
            acc[i][2] = b23.x; acc[i][3] = b23.y;
        }
    }

    #pragma unroll 8
    for (int k = 0; k < DIM; k++) {
        float4 a = *reinterpret_cast<float4*>(&As[k * AS_LD + tx * 4]);
        ulonglong2 w01 = *reinterpret_cast<ulonglong2*>(&Wsh[k * DIM + ty * 8]);
        ulonglong2 w23 = *reinterpret_cast<ulonglong2*>(&Wsh[k * DIM + ty * 8 + 4]);
        u64 wv0 = w01.x, wv1 = w01.y, wv2 = w23.x, wv3 = w23.y;
        float av[4] = {a.x, a.y, a.z, a.w};
        #pragma unroll
        for (int i = 0; i < 4; i++) {
            u64 pa = dup_f32x2(av[i]);
            fma_f32x2(acc[i][0], pa, wv0, acc[i][0]);
            fma_f32x2(acc[i][1], pa, wv1, acc[i][1]);
            fma_f32x2(acc[i][2], pa, wv2, acc[i][2]);
            fma_f32x2(acc[i][3], pa, wv3, acc[i][3]);
        }
    }

    #pragma unroll
    for (int i = 0; i < 4; i++) {
        int local = tx * 4 + i;
        if (local < cnt) {
            float* op = out + (size_t)psh[local] * DIM + ty * 8;
            ulonglong2 r0; r0.x = acc[i][0]; r0.y = acc[i][1];
            ulonglong2 r1; r1.x = acc[i][2]; r1.y = acc[i][3];
            *reinterpret_cast<ulonglong2*>(op)     = r0;
            *reinterpret_cast<ulonglong2*>(op + 4) = r1;
        }
    }
}

// ---------------------------------------------------------------------------
// Launch: memset, bucket_all, fused gather+gemm. Inputs:
// feat, gate_W, gate_b, src, dst, ntype2, act_flag
// ---------------------------------------------------------------------------
extern "C" void kernel_launch(void* const* d_in, const int* in_sizes, int n_in,
                              void* d_out, int out_size) {
    const float* feat   = (const float*)d_in[0];
    const float* gate_W = (const float*)d_in[1];
    const float* gate_b = (const float*)d_in[2];
    const int*   src    = (const int*)d_in[3];
    const int*   dst    = (const int*)d_in[4];
    const int*   ntype2 = (const int*)d_in[5];

    int n = in_sizes[0] / DIM;     // 100000
    int e = in_sizes[3];           // 1000000
    float* out = (float*)d_out;

    void* p_zero = nullptr;
    cudaGetSymbolAddress(&p_zero, g_zero_region);
    cudaMemsetAsync(p_zero, 0, (n + NTYPE) * sizeof(int));

    bucket_all<<<2048, 256>>>(src, dst, ntype2, e, n);

    int fused_smem = (DIM * DIM + DIM * AS_LD) * (int)sizeof(float);   // ~51 KB
    cudaFuncSetAttribute(fused_kernel,
                         cudaFuncAttributeMaxDynamicSharedMemorySize, fused_smem);
    fused_kernel<<<NTYPE * TILES_PER_TYPE, 256, fused_smem>>>(
        feat, gate_W, gate_b, out);
}

// round 7
// speedup vs baseline: 1.0785x; 1.0785x over previous
#include <cuda_runtime.h>

#define DIM    64
#define NTYPE  16
#define NMAX   100000
#define PAD    64          // max in-degree (Poisson(10): P(>=64) ~ 1e-30)
#define PAD_T  8192        // max nodes per type (Binomial(100k,1/16) max ~ 6.6k)
#define TILE_M 128
#define TILES_PER_TYPE (PAD_T / TILE_M)   // 64
#define AS_LD  136

// ---- scratch (device globals; allocation is forbidden) ----
__device__ int   g_zero_region[NMAX + NTYPE];   // [0,NMAX)=deg cnt, [NMAX,..)=type cnt
#define G_CNT(i)  g_zero_region[i]
#define G_TCNT(t) g_zero_region[NMAX + (t)]

__device__ int   g_bucket[(size_t)NMAX * PAD];  // 25.6 MB padded per-dst src lists
__device__ int   g_tperm[NTYPE * PAD_T];        // type-sorted node ids
__device__ float g_neigh[(size_t)NMAX * DIM];   // 25.6 MB mean-aggregated features

typedef unsigned long long u64;

__device__ __forceinline__ void fma_f32x2(u64& d, u64 a, u64 b, u64 c) {
    asm("fma.rn.f32x2 %0, %1, %2, %3;" : "=l"(d) : "l"(a), "l"(b), "l"(c));
}
__device__ __forceinline__ u64 dup_f32x2(float v) {
    u64 r; unsigned u = __float_as_uint(v);
    asm("mov.b64 %0, {%1, %1};" : "=l"(r) : "r"(u));
    return r;
}

// ---------------------------------------------------------------------------
// K1: single-pass bucketing. Edges -> padded per-dst buckets; nodes -> padded
//     per-type perm via block-aggregated smem atomics.
// ---------------------------------------------------------------------------
__global__ void bucket_all(const int* __restrict__ src,
                           const int* __restrict__ dst,
                           const int* __restrict__ ntype2, int e, int n) {
    __shared__ int h[NTYPE];
    __shared__ int hbase[NTYPE];

    int stride = gridDim.x * blockDim.x;
    int tid = blockIdx.x * blockDim.x + threadIdx.x;

    for (int i = tid; i < e; i += stride) {
        int d = dst[i];
        int s = src[i];
        int pos = atomicAdd(&G_CNT(d), 1);
        if (pos < PAD) g_bucket[(size_t)d * PAD + pos] = s;
    }

    if (threadIdx.x < NTYPE) h[threadIdx.x] = 0;
    __syncthreads();

    int per_block = (n + gridDim.x - 1) / gridDim.x;
    int nb = blockIdx.x * per_block;
    int ne = min(nb + per_block, n);

    for (int i = nb + threadIdx.x; i < ne; i += blockDim.x)
        atomicAdd(&h[ntype2[i]], 1);
    __syncthreads();
    if (threadIdx.x < NTYPE) {
        if (h[threadIdx.x] > 0)
            hbase[threadIdx.x] = atomicAdd(&G_TCNT(threadIdx.x), h[threadIdx.x]);
        h[threadIdx.x] = 0;
    }
    __syncthreads();
    for (int i = nb + threadIdx.x; i < ne; i += blockDim.x) {
        int t = ntype2[i];
        int lp = atomicAdd(&h[t], 1);
        int p = hbase[t] + lp;
        if (p < PAD_T) g_tperm[t * PAD_T + p] = i;
    }
}

// ---------------------------------------------------------------------------
// K2: gather-mean. Warp per dst node; 4 independent warp-uniform index loads
//     keep 4 feature-row loads in flight. High occupancy hides L2 latency.
// ---------------------------------------------------------------------------
__global__ void gather_kernel(const float* __restrict__ feat, int n) {
    int warp = (blockIdx.x * blockDim.x + threadIdx.x) >> 5;
    int lane = threadIdx.x & 31;
    if (warp >= n) return;

    int deg = G_CNT(warp);
    int cnt = min(deg, PAD);
    const int* row = g_bucket + (size_t)warp * PAD;

    const float2* feat2 = reinterpret_cast<const float2*>(feat);
    float2 acc0 = make_float2(0.f, 0.f);
    float2 acc1 = make_float2(0.f, 0.f);

    int j = 0;
    for (; j + 4 <= cnt; j += 4) {
        int s0 = __ldg(&row[j]);
        int s1 = __ldg(&row[j + 1]);
        int s2 = __ldg(&row[j + 2]);
        int s3 = __ldg(&row[j + 3]);
        float2 a0 = feat2[(size_t)s0 * 32 + lane];
        float2 a1 = feat2[(size_t)s1 * 32 + lane];
        float2 a2 = feat2[(size_t)s2 * 32 + lane];
        float2 a3 = feat2[(size_t)s3 * 32 + lane];
        acc0.x += a0.x + a1.x;  acc0.y += a0.y + a1.y;
        acc1.x += a2.x + a3.x;  acc1.y += a2.y + a3.y;
    }
    for (; j < cnt; j++) {
        int s0 = __ldg(&row[j]);
        float2 a = feat2[(size_t)s0 * 32 + lane];
        acc0.x += a.x;  acc0.y += a.y;
    }

    float invd = (deg > 0) ? (1.0f / (float)deg) : 0.0f;
    float2 r;
    r.x = (acc0.x + acc1.x) * invd;
    r.y = (acc0.y + acc1.y) * invd;
    reinterpret_cast<float2*>(g_neigh)[(size_t)warp * 32 + lane] = r;
}

// ---------------------------------------------------------------------------
// K3: tiled GEMM over type-sorted nodes, packed fma.rn.f32x2 (2x fp32 tput).
//     Block = (type, tile); thread = 4 nodes x 8 outs.
// ---------------------------------------------------------------------------
__global__ void __launch_bounds__(256) gemm_kernel(
        const float* __restrict__ gate_W,
        const float* __restrict__ gate_b,
        float* __restrict__ out) {
    int t    = blockIdx.x / TILES_PER_TYPE;
    int tile = blockIdx.x % TILES_PER_TYPE;

    int tcnt  = min(G_TCNT(t), PAD_T);
    int start = tile * TILE_M;
    if (start >= tcnt) return;
    int cnt = min(TILE_M, tcnt - start);

    extern __shared__ float sm[];
    float* Wsh = sm;                    // [64][64]
    float* As  = sm + DIM * DIM;        // [64][AS_LD]
    __shared__ int   psh[TILE_M];
    __shared__ float bsh[DIM];

    if (threadIdx.x < TILE_M)
        psh[threadIdx.x] = (threadIdx.x < cnt)
            ? g_tperm[t * PAD_T + start + threadIdx.x] : -1;
    const float* Wt = gate_W + (size_t)t * DIM * DIM;
    for (int i = threadIdx.x; i < DIM * DIM; i += 256)
        Wsh[i] = Wt[i];
    if (threadIdx.x < DIM)
        bsh[threadIdx.x] = gate_b[t * DIM + threadIdx.x];
    __syncthreads();

    {   // stage A transposed: As[k][node]
        int row  = threadIdx.x >> 1;
        int half = threadIdx.x & 1;
        const float4* srcp = (row < cnt)
            ? reinterpret_cast<const float4*>(g_neigh + (size_t)psh[row] * DIM)
            : nullptr;
        #pragma unroll
        for (int j = 0; j < 8; j++) {
            int k = half * 32 + j * 4;
            float4 v = (row < cnt) ? srcp[k >> 2] : make_float4(0.f, 0.f, 0.f, 0.f);
            As[(k + 0) * AS_LD + row] = v.x;
            As[(k + 1) * AS_LD + row] = v.y;
            As[(k + 2) * AS_LD + row] = v.z;
            As[(k + 3) * AS_LD + row] = v.w;
        }
    }
    __syncthreads();

    int tx = threadIdx.x & 31;
    int ty = threadIdx.x >> 5;

    u64 acc[4][4];
    {
        ulonglong2 b01 = *reinterpret_cast<ulonglong2*>(&bsh[ty * 8]);
        ulonglong2 b23 = *reinterpret_cast<ulonglong2*>(&bsh[ty * 8 + 4]);
        #pragma unroll
        for (int i = 0; i < 4; i++) {
            acc[i][0] = b01.x; acc[i][1] = b01.y;
            acc[i][2] = b23.x; acc[i][3] = b23.y;
        }
    }

    #pragma unroll 8
    for (int k = 0; k < DIM; k++) {
        float4 a = *reinterpret_cast<float4*>(&As[k * AS_LD + tx * 4]);
        ulonglong2 w01 = *reinterpret_cast<ulonglong2*>(&Wsh[k * DIM + ty * 8]);
        ulonglong2 w23 = *reinterpret_cast<ulonglong2*>(&Wsh[k * DIM + ty * 8 + 4]);
        u64 wv0 = w01.x, wv1 = w01.y, wv2 = w23.x, wv3 = w23.y;
        float av[4] = {a.x, a.y, a.z, a.w};
        #pragma unroll
        for (int i = 0; i < 4; i++) {
            u64 pa = dup_f32x2(av[i]);
            fma_f32x2(acc[i][0], pa, wv0, acc[i][0]);
            fma_f32x2(acc[i][1], pa, wv1, acc[i][1]);
            fma_f32x2(acc[i][2], pa, wv2, acc[i][2]);
            fma_f32x2(acc[i][3], pa, wv3, acc[i][3]);
        }
    }

    #pragma unroll
    for (int i = 0; i < 4; i++) {
        int local = tx * 4 + i;
        if (local < cnt) {
            float* op = out + (size_t)psh[local] * DIM + ty * 8;
            ulonglong2 r0; r0.x = acc[i][0]; r0.y = acc[i][1];
            ulonglong2 r1; r1.x = acc[i][2]; r1.y = acc[i][3];
            *reinterpret_cast<ulonglong2*>(op)     = r0;
            *reinterpret_cast<ulonglong2*>(op + 4) = r1;
        }
    }
}

// ---------------------------------------------------------------------------
// Launch: memset, bucket_all, gather, gemm.
// Inputs: feat, gate_W, gate_b, src, dst, ntype2, act_flag
// ---------------------------------------------------------------------------
extern "C" void kernel_launch(void* const* d_in, const int* in_sizes, int n_in,
                              void* d_out, int out_size) {
    const float* feat   = (const float*)d_in[0];
    const float* gate_W = (const float*)d_in[1];
    const float* gate_b = (const float*)d_in[2];
    const int*   src    = (const int*)d_in[3];
    const int*   dst    = (const int*)d_in[4];
    const int*   ntype2 = (const int*)d_in[5];

    int n = in_sizes[0] / DIM;     // 100000
    int e = in_sizes[3];           // 1000000
    float* out = (float*)d_out;

    void* p_zero = nullptr;
    cudaGetSymbolAddress(&p_zero, g_zero_region);
    cudaMemsetAsync(p_zero, 0, (n + NTYPE) * sizeof(int));

    bucket_all<<<2048, 256>>>(src, dst, ntype2, e, n);
    gather_kernel<<<(n * 32 + 255) / 256, 256>>>(feat, n);

    int gemm_smem = (DIM * DIM + DIM * AS_LD) * (int)sizeof(float);
    cudaFuncSetAttribute(gemm_kernel,
                         cudaFuncAttributeMaxDynamicSharedMemorySize, gemm_smem);
    gemm_kernel<<<NTYPE * TILES_PER_TYPE, 256, gemm_smem>>>(gate_W, gate_b, out);
}